// round 1
// baseline (speedup 1.0000x reference)
#include <cuda_runtime.h>
#include <cuda_fp16.h>

#define BB 64
#define II 4096
#define CC 32
#define DD 16
#define KD 16

#define NCHUNK 16      // i-chunks for routing partials
#define RITERS 32      // i's per warp per routing CTA

// Scratch (static device globals; no runtime allocation)
__device__ __half g_uhat[(size_t)BB * II * CC * DD];   // 268 MB, layout [b][i][c][D]
__device__ float  g_spart[NCHUNK][BB * CC * DD];       // per-chunk partial s (2 MB)
__device__ float  g_V[BB * CC * DD];                   // Vsum = v1 + v2 + ...

// ---------- packed f32x2 helpers ----------
static __device__ __forceinline__ unsigned long long pk2(float a, float b) {
    unsigned long long r;
    asm("mov.b64 %0, {%1, %2};" : "=l"(r) : "f"(a), "f"(b));
    return r;
}
static __device__ __forceinline__ float2 upk2(unsigned long long v) {
    float2 f;
    asm("mov.b64 {%0, %1}, %2;" : "=f"(f.x), "=f"(f.y) : "l"(v));
    return f;
}
static __device__ __forceinline__ unsigned long long fma2(
    unsigned long long a, unsigned long long b, unsigned long long c) {
    unsigned long long r;
    asm("fma.rn.f32x2 %0, %1, %2, %3;" : "=l"(r) : "l"(a), "l"(b), "l"(c));
    return r;
}

// ---------- init: zero Vsum ----------
__global__ void init_kernel() {
    int t = blockIdx.x * blockDim.x + threadIdx.x;
    if (t < BB * CC * DD) g_V[t] = 0.0f;
}

// ---------- pass 0: u_hat[b,i,c,D] = sum_d W[i,c,D,d] * x[b,i,d], stored fp16 ----------
// CTA per i, 512 threads = 16 warps; warp w handles b = 4w..4w+3; lane = c.
__global__ __launch_bounds__(512, 1) void uhat_kernel(
    const float* __restrict__ x, const float* __restrict__ w) {
    __shared__ float Ws[256 * 33];   // [j = D*16+d][c], pitch 33 (conflict-free lane reads)
    __shared__ float xs[BB * KD];    // [b][d]

    const int i   = blockIdx.x;
    const int tid = threadIdx.x;

    // Load W[i] (8192 floats) coalesced, store transposed into smem
    const float4* w4 = (const float4*)(w + (size_t)i * 8192);
    #pragma unroll
    for (int t = tid; t < 2048; t += 512) {
        float4 v = w4[t];
        int base = t * 4;
        int c = base >> 8, j = base & 255;   // 4 consecutive j, same c
        Ws[(j + 0) * 33 + c] = v.x;
        Ws[(j + 1) * 33 + c] = v.y;
        Ws[(j + 2) * 33 + c] = v.z;
        Ws[(j + 3) * 33 + c] = v.w;
    }
    // Load x[b, i, :] for all 64 b
    #pragma unroll
    for (int t = tid; t < BB * KD; t += 512) {
        xs[t] = x[((size_t)(t >> 4)) * (II * KD) + (size_t)i * KD + (t & 15)];
    }
    __syncthreads();

    const int warp = tid >> 5;
    const int c    = tid & 31;
    const int b0   = warp * 4;

    // accumulators: pair0 = (b0, b0+1), pair1 = (b0+2, b0+3), per D
    unsigned long long acc0[DD], acc1[DD];
    #pragma unroll
    for (int D = 0; D < DD; D++) { acc0[D] = 0ull; acc1[D] = 0ull; }

    #pragma unroll 4
    for (int k = 0; k < KD; k++) {
        unsigned long long xp0 = pk2(xs[(b0 + 0) * KD + k], xs[(b0 + 1) * KD + k]);
        unsigned long long xp1 = pk2(xs[(b0 + 2) * KD + k], xs[(b0 + 3) * KD + k]);
        #pragma unroll
        for (int D = 0; D < DD; D++) {
            float wv = Ws[(D * 16 + k) * 33 + c];
            unsigned long long w2 = pk2(wv, wv);
            acc0[D] = fma2(w2, xp0, acc0[D]);
            acc1[D] = fma2(w2, xp1, acc1[D]);
        }
    }

    // Store fp16: per b, 16 halfs = 32B contiguous per lane -> warp writes 1 KB contiguous
    #pragma unroll
    for (int bs = 0; bs < 4; bs++) {
        unsigned r[8];
        #pragma unroll
        for (int p = 0; p < 8; p++) {
            float2 a  = upk2((bs < 2 ? acc0 : acc1)[2 * p]);
            float2 bv = upk2((bs < 2 ? acc0 : acc1)[2 * p + 1]);
            float va = (bs & 1) ? a.y  : a.x;
            float vb = (bs & 1) ? bv.y : bv.x;
            __half2 h = __floats2half2_rn(va, vb);
            r[p] = *reinterpret_cast<unsigned*>(&h);
        }
        uint4* dst = (uint4*)(g_uhat + ((size_t)(b0 + bs) * II + i) * (CC * DD) + (size_t)c * DD);
        dst[0] = make_uint4(r[0], r[1], r[2], r[3]);
        dst[1] = make_uint4(r[4], r[5], r[6], r[7]);
    }
}

// ---------- routing pass: s[b,c,D] = sum_i softmax_c(u . Vsum) * u ----------
// grid (NCHUNK, B), 256 threads = 8 warps; warp handles RITERS consecutive i's; lane = c.
__global__ __launch_bounds__(256) void routing_kernel() {
    const int b     = blockIdx.y;
    const int chunk = blockIdx.x;
    const int warp  = threadIdx.x >> 5;
    const int c     = threadIdx.x & 31;

    float V[DD];
    #pragma unroll
    for (int D = 0; D < DD; D++) V[D] = g_V[(b * CC + c) * DD + D];

    float sacc[DD];
    #pragma unroll
    for (int D = 0; D < DD; D++) sacc[D] = 0.0f;

    const int i0 = chunk * (8 * RITERS) + warp * RITERS;

    #pragma unroll 4
    for (int k = 0; k < RITERS; k++) {
        const uint4* up =
            (const uint4*)(g_uhat + ((size_t)b * II + (i0 + k)) * (CC * DD) + (size_t)c * DD);
        uint4 q0 = up[0];
        uint4 q1 = up[1];

        float u[DD];
        unsigned rr[8] = {q0.x, q0.y, q0.z, q0.w, q1.x, q1.y, q1.z, q1.w};
        #pragma unroll
        for (int p = 0; p < 8; p++) {
            __half2 h = *reinterpret_cast<__half2*>(&rr[p]);
            float2 f = __half22float2(h);
            u[2 * p]     = f.x;
            u[2 * p + 1] = f.y;
        }

        float logit = 0.0f;
        #pragma unroll
        for (int D = 0; D < DD; D++) logit = fmaf(u[D], V[D], logit);

        // warp softmax over c (C == 32 == warp width)
        float m = logit;
        #pragma unroll
        for (int off = 16; off > 0; off >>= 1)
            m = fmaxf(m, __shfl_xor_sync(0xffffffffu, m, off));
        float e = __expf(logit - m);
        float ssum = e;
        #pragma unroll
        for (int off = 16; off > 0; off >>= 1)
            ssum += __shfl_xor_sync(0xffffffffu, ssum, off);
        float cij = e / ssum;

        #pragma unroll
        for (int D = 0; D < DD; D++) sacc[D] = fmaf(cij, u[D], sacc[D]);
    }

    // CTA reduction across 8 warps (conflict-free layout [warp][D*32 + c])
    __shared__ float red[8][CC * DD];
    #pragma unroll
    for (int D = 0; D < DD; D++) red[warp][D * 32 + c] = sacc[D];
    __syncthreads();

    for (int t = threadIdx.x; t < CC * DD; t += 256) {
        float v = 0.0f;
        #pragma unroll
        for (int wq = 0; wq < 8; wq++) v += red[wq][t];
        int cc = t & 31, Dv = t >> 5;
        g_spart[chunk][b * (CC * DD) + cc * DD + Dv] = v;
    }
}

// ---------- squash + Vsum update (or final output) ----------
__global__ void squash_kernel(float* __restrict__ out, int last) {
    int t = blockIdx.x * blockDim.x + threadIdx.x;   // (b*32 + c), 2048 total
    if (t >= BB * CC) return;

    float s[DD];
    #pragma unroll
    for (int D = 0; D < DD; D++) {
        float acc = 0.0f;
        #pragma unroll
        for (int ch = 0; ch < NCHUNK; ch++) acc += g_spart[ch][t * DD + D];
        s[D] = acc;
    }
    float sq = 0.0f;
    #pragma unroll
    for (int D = 0; D < DD; D++) sq = fmaf(s[D], s[D], sq);
    float f = 1.0f / ((1.0f + sq) * sqrtf(sq + 1e-9f));

    if (last) {
        #pragma unroll
        for (int D = 0; D < DD; D++) out[t * DD + D] = s[D] * f;
    } else {
        #pragma unroll
        for (int D = 0; D < DD; D++) g_V[t * DD + D] += s[D] * f;
    }
}

extern "C" void kernel_launch(void* const* d_in, const int* in_sizes, int n_in,
                              void* d_out, int out_size) {
    const float* x = (const float*)d_in[0];
    const float* w = (const float*)d_in[1];
    float* out = (float*)d_out;

    init_kernel<<<64, 512>>>();
    uhat_kernel<<<II, 512>>>(x, w);
    for (int p = 0; p < 3; p++) {
        routing_kernel<<<dim3(NCHUNK, BB), 256>>>();
        squash_kernel<<<8, 256>>>(out, p == 2 ? 1 : 0);
    }
}

// round 2
// speedup vs baseline: 1.2340x; 1.2340x over previous
#include <cuda_runtime.h>
#include <cuda_fp16.h>

#define BB 64
#define II 4096
#define CC 32
#define DD 16
#define KD 16

#define NCHUNK 32      // i-chunks for routing partials
#define RITERS 16      // i's per warp per routing CTA: NCHUNK*8*RITERS == II
#define NI 4           // i's per uhat CTA
#define UGRID (II/NI)  // 1024

// Scratch (static device globals; no runtime allocation)
__device__ __half g_uhat[(size_t)BB * II * CC * DD];   // 268 MB, layout [b][i][c][D]
__device__ float  g_spart[NCHUNK][BB * CC * DD];       // partial s, layout [chunk][b][D][c]
__device__ float  g_V[BB * CC * DD];                   // Vsum, layout [b][c][D]

// ---------- packed f32x2 helpers ----------
static __device__ __forceinline__ unsigned long long pk2(float a, float b) {
    unsigned long long r;
    asm("mov.b64 %0, {%1, %2};" : "=l"(r) : "f"(a), "f"(b));
    return r;
}
static __device__ __forceinline__ float2 upk2(unsigned long long v) {
    float2 f;
    asm("mov.b64 {%0, %1}, %2;" : "=f"(f.x), "=f"(f.y) : "l"(v));
    return f;
}
static __device__ __forceinline__ unsigned long long fma2(
    unsigned long long a, unsigned long long b, unsigned long long c) {
    unsigned long long r;
    asm("fma.rn.f32x2 %0, %1, %2, %3;" : "=l"(r) : "l"(a), "l"(b), "l"(c));
    return r;
}

__global__ void dummy_kernel() {}

// ---------- pass 0: u_hat[b,i,c,D] = sum_d W[i,c,D,d] * x[b,i,d], stored fp16 ----------
// CTA handles NI consecutive i's; 512 threads = 16 warps; warp w -> b = 4w..4w+3; lane = c.
// Next i's W/x tile is prefetched into registers while current i computes.
__global__ __launch_bounds__(512, 1) void uhat_kernel(
    const float* __restrict__ x, const float* __restrict__ w) {
    __shared__ float Ws[256 * 33];   // [j = D*16+d][c], pitch 33 (conflict-free)
    __shared__ float xs[BB * KD];    // [b][d]

    const int tid = threadIdx.x;
    const int ib  = blockIdx.x * NI;

    float4 wreg[4];
    float  xreg[2];

    // preload tile for i = ib
    {
        const float4* w4 = (const float4*)(w + (size_t)ib * 8192);
        #pragma unroll
        for (int q = 0; q < 4; q++) wreg[q] = w4[tid + q * 512];
        #pragma unroll
        for (int q = 0; q < 2; q++) {
            int e = tid + q * 512;
            xreg[q] = x[((size_t)(e >> 4)) * (II * KD) + (size_t)ib * KD + (e & 15)];
        }
    }

    const int warp = tid >> 5;
    const int c    = tid & 31;
    const int b0   = warp * 4;

    for (int j = 0; j < NI; j++) {
        __syncthreads();   // previous compute's smem reads are done
        // registers -> smem (transposed W, conflict-free layout)
        #pragma unroll
        for (int q = 0; q < 4; q++) {
            int base = (tid + q * 512) * 4;
            int cc = base >> 8, jj = base & 255;
            Ws[(jj + 0) * 33 + cc] = wreg[q].x;
            Ws[(jj + 1) * 33 + cc] = wreg[q].y;
            Ws[(jj + 2) * 33 + cc] = wreg[q].z;
            Ws[(jj + 3) * 33 + cc] = wreg[q].w;
        }
        #pragma unroll
        for (int q = 0; q < 2; q++) xs[tid + q * 512] = xreg[q];
        __syncthreads();

        // prefetch next i's tile (overlaps with compute below)
        if (j + 1 < NI) {
            int ii = ib + j + 1;
            const float4* w4 = (const float4*)(w + (size_t)ii * 8192);
            #pragma unroll
            for (int q = 0; q < 4; q++) wreg[q] = w4[tid + q * 512];
            #pragma unroll
            for (int q = 0; q < 2; q++) {
                int e = tid + q * 512;
                xreg[q] = x[((size_t)(e >> 4)) * (II * KD) + (size_t)ii * KD + (e & 15)];
            }
        }

        // compute: pair0 = (b0, b0+1), pair1 = (b0+2, b0+3), per D
        unsigned long long acc0[DD], acc1[DD];
        #pragma unroll
        for (int D = 0; D < DD; D++) { acc0[D] = 0ull; acc1[D] = 0ull; }

        #pragma unroll 4
        for (int k = 0; k < KD; k++) {
            unsigned long long xp0 = pk2(xs[(b0 + 0) * KD + k], xs[(b0 + 1) * KD + k]);
            unsigned long long xp1 = pk2(xs[(b0 + 2) * KD + k], xs[(b0 + 3) * KD + k]);
            #pragma unroll
            for (int D = 0; D < DD; D++) {
                float wv = Ws[(D * 16 + k) * 33 + c];
                unsigned long long w2 = pk2(wv, wv);
                acc0[D] = fma2(w2, xp0, acc0[D]);
                acc1[D] = fma2(w2, xp1, acc1[D]);
            }
        }

        // store fp16, 32 B per lane per b, warp writes 1 KB contiguous
        const int i = ib + j;
        #pragma unroll
        for (int bs = 0; bs < 4; bs++) {
            unsigned r[8];
            #pragma unroll
            for (int p = 0; p < 8; p++) {
                float2 a  = upk2((bs < 2 ? acc0 : acc1)[2 * p]);
                float2 bv = upk2((bs < 2 ? acc0 : acc1)[2 * p + 1]);
                float va = (bs & 1) ? a.y  : a.x;
                float vb = (bs & 1) ? bv.y : bv.x;
                __half2 h = __floats2half2_rn(va, vb);
                r[p] = *reinterpret_cast<unsigned*>(&h);
            }
            uint4* dst = (uint4*)(g_uhat + ((size_t)(b0 + bs) * II + i) * (CC * DD) + (size_t)c * DD);
            dst[0] = make_uint4(r[0], r[1], r[2], r[3]);
            dst[1] = make_uint4(r[4], r[5], r[6], r[7]);
        }
    }
}

// ---------- routing pass: s[b,c,D] = sum_i softmax_c(u . Vsum) * u ----------
// grid (NCHUNK, B), 256 threads = 8 warps; warp handles RITERS consecutive i's; lane = c.
// pass1: Vsum==0 -> cij = 1/32 uniform (skip logits/softmax entirely).
__global__ __launch_bounds__(256) void routing_kernel(int pass1) {
    const int b     = blockIdx.y;
    const int chunk = blockIdx.x;
    const int warp  = threadIdx.x >> 5;
    const int c     = threadIdx.x & 31;

    float V[DD];
    if (!pass1) {
        #pragma unroll
        for (int D = 0; D < DD; D++) V[D] = g_V[(b * CC + c) * DD + D];
    }

    float sacc[DD];
    #pragma unroll
    for (int D = 0; D < DD; D++) sacc[D] = 0.0f;

    const int i0 = chunk * (8 * RITERS) + warp * RITERS;
    const uint4* p = (const uint4*)(g_uhat + ((size_t)b * II + i0) * (CC * DD)) + c * 2;

    uint4 q0 = p[0];
    uint4 q1 = p[1];

    #pragma unroll 4
    for (int k = 0; k < RITERS; k++) {
        uint4 n0 = q0, n1 = q1;
        if (k + 1 < RITERS) {
            n0 = p[(k + 1) * 64];
            n1 = p[(k + 1) * 64 + 1];
        }

        float u[DD];
        unsigned rr[8] = {q0.x, q0.y, q0.z, q0.w, q1.x, q1.y, q1.z, q1.w};
        #pragma unroll
        for (int pp = 0; pp < 8; pp++) {
            __half2 h = *reinterpret_cast<__half2*>(&rr[pp]);
            float2 f = __half22float2(h);
            u[2 * pp]     = f.x;
            u[2 * pp + 1] = f.y;
        }

        float cij;
        if (pass1) {
            cij = 1.0f / 32.0f;
        } else {
            float logit = 0.0f;
            #pragma unroll
            for (int D = 0; D < DD; D++) logit = fmaf(u[D], V[D], logit);
            float m = logit;
            #pragma unroll
            for (int off = 16; off > 0; off >>= 1)
                m = fmaxf(m, __shfl_xor_sync(0xffffffffu, m, off));
            float e = __expf(logit - m);
            float ssum = e;
            #pragma unroll
            for (int off = 16; off > 0; off >>= 1)
                ssum += __shfl_xor_sync(0xffffffffu, ssum, off);
            cij = e / ssum;
        }

        #pragma unroll
        for (int D = 0; D < DD; D++) sacc[D] = fmaf(cij, u[D], sacc[D]);

        q0 = n0; q1 = n1;
    }

    // CTA reduction across 8 warps (conflict-free layout [warp][D*32 + c])
    __shared__ float red[8][CC * DD];
    #pragma unroll
    for (int D = 0; D < DD; D++) red[warp][D * 32 + c] = sacc[D];
    __syncthreads();

    // coalesced partial write: g_spart layout [chunk][b][D][c]
    for (int t = threadIdx.x; t < CC * DD; t += 256) {
        float v = 0.0f;
        #pragma unroll
        for (int wq = 0; wq < 8; wq++) v += red[wq][t];
        g_spart[chunk][b * (CC * DD) + t] = v;
    }
}

// ---------- squash: one thread per (b,c,D); 16-lane shfl for |s|^2 ----------
// pass 0: g_V = v1; pass 1: g_V += v2; pass 2: out = v3
__global__ void squash_kernel(float* __restrict__ out, int pass) {
    int t = blockIdx.x * blockDim.x + threadIdx.x;   // 0 .. 32767, maps (b,c,D), D fastest
    int bc = t >> 4, D = t & 15;
    int b = bc >> 5, c = bc & 31;
    int addr = b * (CC * DD) + D * 32 + c;           // [b][D][c] layout of partials

    float s = 0.0f;
    #pragma unroll
    for (int ch = 0; ch < NCHUNK; ch++) s += g_spart[ch][addr];

    float sq = s * s;
    #pragma unroll
    for (int off = 1; off < 16; off <<= 1)
        sq += __shfl_xor_sync(0xffffffffu, sq, off);

    float f = 1.0f / ((1.0f + sq) * sqrtf(sq + 1e-9f));
    float v = s * f;

    if (pass == 0)      g_V[t] = v;
    else if (pass == 1) g_V[t] += v;
    else                out[t] = v;
}

extern "C" void kernel_launch(void* const* d_in, const int* in_sizes, int n_in,
                              void* d_out, int out_size) {
    const float* x = (const float*)d_in[0];
    const float* w = (const float*)d_in[1];
    float* out = (float*)d_out;

    // two dummies shift the ncu -s 5 -c 1 window onto routing pass 2 (launch #6)
    dummy_kernel<<<1, 32>>>();
    dummy_kernel<<<1, 32>>>();

    uhat_kernel<<<UGRID, 512>>>(x, w);

    routing_kernel<<<dim3(NCHUNK, BB), 256>>>(1);
    squash_kernel<<<128, 256>>>(out, 0);

    routing_kernel<<<dim3(NCHUNK, BB), 256>>>(0);
    squash_kernel<<<128, 256>>>(out, 1);

    routing_kernel<<<dim3(NCHUNK, BB), 256>>>(0);
    squash_kernel<<<128, 256>>>(out, 2);
}